// round 2
// baseline (speedup 1.0000x reference)
#include <cuda_runtime.h>
#include <math.h>

#define NB 16
#define NF 48
#define NM 51
#define HH 256
#define WW 256
#define LUTN 3201
#define NPIX (NB*HH*WW)

// scratch (no allocations allowed)
__device__ float g_wn[NF*49];
__device__ float g_lut[NF*LUTN];
__device__ float g_sums[NB];
__device__ float g_r[NPIX];

// ---------------------------------------------------------------------------
// Prep: normalize conv weights, build per-filter RBF LUT, zero batch sums.
// One block per filter.
// ---------------------------------------------------------------------------
__global__ void prep_kernel(const float* __restrict__ cw,
                            const float* __restrict__ scale_f,
                            const float* __restrict__ rbfw,
                            const float* __restrict__ rbfc) {
    int f = blockIdx.x;
    int t = threadIdx.x;
    __shared__ float sw[49];
    __shared__ float s_norm[2];
    __shared__ float s_wm[NM];
    __shared__ float s_c[NM];
    if (t < 49) sw[t] = cw[f*49 + t];
    if (t < NM) { s_wm[t] = rbfw[f*NM + t]; s_c[t] = rbfc[t]; }
    if (t == 0 && f < NB) g_sums[f] = 0.f;
    __syncthreads();
    if (t == 0) {
        float m = 0.f;
        for (int i = 0; i < 49; i++) m += sw[i];
        m *= (1.f/49.f);
        float ss = 0.f;
        for (int i = 0; i < 49; i++) { float v = sw[i]-m; ss += v*v; }
        s_norm[0] = m;
        s_norm[1] = scale_f[f] / (sqrtf(ss) + 1e-12f);
    }
    __syncthreads();
    if (t < 49) g_wn[f*49 + t] = (sw[t] - s_norm[0]) * s_norm[1];
    for (int i = t; i < LUTN; i += blockDim.x) {
        float x = -100.f + (float)i * 0.0625f;
        float acc = 0.f;
        #pragma unroll 1
        for (int m = 0; m < NM; m++) {
            float d = x - s_c[m];
            acc += s_wm[m] * __expf(-0.01f * d * d);
        }
        g_lut[f*LUTN + i] = acc;
    }
}

// ---------------------------------------------------------------------------
// Main fused kernel: fwd conv -> RBF LUT -> transpose conv -> residual r,
// plus per-batch sum(r^2) via block reduce + atomicAdd.
// One CTA = 32x32 output tile. z/a region = 38x38 (a=0 outside [0,255]).
// Input tile (with symmetric reflect) = 44x44.
// ---------------------------------------------------------------------------
__global__ void __launch_bounds__(256, 2)
main_kernel(const float* __restrict__ input, const float* __restrict__ net_input) {
    __shared__ float s_in[44][48];      // stride 48 (16B-aligned rows)
    __shared__ float s_a[38][40];
    __shared__ float s_wall[NF*49];
    __shared__ float s_red[8];

    int t = threadIdx.x;
    int b = blockIdx.z;
    int ty0 = blockIdx.y << 5;
    int tx0 = blockIdx.x << 5;
    const float* inb = input + b*(HH*WW);

    // load input halo tile with symmetric reflection (pad 'symmetric')
    for (int idx = t; idx < 44*44; idx += 256) {
        int iy = idx / 44, ix = idx - iy*44;
        int gy = ty0 - 6 + iy, gx = tx0 - 6 + ix;
        gy = gy < 0 ? -1-gy : (gy > 255 ? 511-gy : gy);
        gx = gx < 0 ? -1-gx : (gx > 255 ? 511-gx : gx);
        s_in[iy][ix] = inb[(gy<<8) + gx];
    }
    // all normalized weights into smem once
    for (int idx = t; idx < NF*49; idx += 256) s_wall[idx] = g_wn[idx];

    float acc0=0.f, acc1=0.f, acc2=0.f, acc3=0.f;
    int orow = t >> 3;            // 0..31
    int ocol = (t & 7) << 2;      // 0..28

    int zr = t / 5;               // z-task: 38 rows x 5 groups of 8 cols
    int zg = (t - zr*5) << 3;
    bool zact = (t < 190);
    int zgr = ty0 - 3 + zr;
    int zgc0 = tx0 - 3 + zg;
    bool rowok = (zgr >= 0) && (zgr < 256);

    for (int f = 0; f < NF; f++) {
        const float* wf   = &s_wall[f*49];
        const float* lutf = &g_lut[f*LUTN];
        __syncthreads();   // prev transpose reads of s_a done; (first iter: tiles loaded)
        if (zact) {
            float z0=0,z1=0,z2=0,z3=0,z4=0,z5=0,z6=0,z7=0;
            #pragma unroll
            for (int u = 0; u < 7; u++) {
                const float* rp = &s_in[zr+u][zg];
                float4 p0 = *(const float4*)(rp);
                float4 p1 = *(const float4*)(rp+4);
                float4 p2 = *(const float4*)(rp+8);
                float2 p3 = *(const float2*)(rp+12);
                float vals[14] = {p0.x,p0.y,p0.z,p0.w, p1.x,p1.y,p1.z,p1.w,
                                  p2.x,p2.y,p2.z,p2.w, p3.x,p3.y};
                #pragma unroll
                for (int v = 0; v < 7; v++) {
                    float w = wf[u*7+v];
                    z0 = fmaf(vals[v+0], w, z0);
                    z1 = fmaf(vals[v+1], w, z1);
                    z2 = fmaf(vals[v+2], w, z2);
                    z3 = fmaf(vals[v+3], w, z3);
                    z4 = fmaf(vals[v+4], w, z4);
                    z5 = fmaf(vals[v+5], w, z5);
                    z6 = fmaf(vals[v+6], w, z6);
                    z7 = fmaf(vals[v+7], w, z7);
                }
            }
            float zv[8] = {z0,z1,z2,z3,z4,z5,z6,z7};
            #pragma unroll
            for (int k = 0; k < 8; k++) {
                float a = 0.f;
                int zgc = zgc0 + k;
                if (rowok && zgc >= 0 && zgc < 256) {
                    // clip(z,-100,100) folded into index clamp; NaN-safe via fmaxf
                    float tf = fminf(fmaxf(fmaf(zv[k], 16.f, 1600.f), 0.f), 3200.f);
                    int i0 = (int)tf;
                    i0 = min(i0, 3199);
                    float fr = tf - (float)i0;
                    float l0 = __ldg(lutf + i0);
                    float l1 = __ldg(lutf + i0 + 1);
                    a = fmaf(fr, l1 - l0, l0);
                }
                s_a[zr][zg+k] = a;
            }
        }
        __syncthreads();   // a ready
        // transpose conv: out[y,x] += sum_{u,v} w[u,v] * a[y+6-u, x+6-v]
        #pragma unroll
        for (int uu = 0; uu < 7; uu++) {
            const float* rp = &s_a[orow+uu][ocol];
            float4 p0 = *(const float4*)(rp);
            float4 p1 = *(const float4*)(rp+4);
            float2 p2 = *(const float2*)(rp+8);
            float vals[10] = {p0.x,p0.y,p0.z,p0.w, p1.x,p1.y,p1.z,p1.w, p2.x,p2.y};
            #pragma unroll
            for (int vv = 0; vv < 7; vv++) {
                float w = wf[(6-uu)*7 + (6-vv)];
                acc0 = fmaf(vals[vv+0], w, acc0);
                acc1 = fmaf(vals[vv+1], w, acc1);
                acc2 = fmaf(vals[vv+2], w, acc2);
                acc3 = fmaf(vals[vv+3], w, acc3);
            }
        }
    }

    // residual r = input - convt - net_input; write r, reduce r^2 per batch
    int gy = ty0 + orow;
    int gx = tx0 + ocol;
    int base = (gy<<8) + gx;
    const float* nb_ = net_input + b*(HH*WW);
    float4 iv = *(const float4*)(inb + base);
    float4 nv = *(const float4*)(nb_ + base);
    float r0 = iv.x - acc0 - nv.x;
    float r1 = iv.y - acc1 - nv.y;
    float r2 = iv.z - acc2 - nv.z;
    float r3 = iv.w - acc3 - nv.w;
    float4 rv; rv.x=r0; rv.y=r1; rv.z=r2; rv.w=r3;
    *(float4*)(g_r + b*(HH*WW) + base) = rv;
    float ls = r0*r0 + r1*r1 + r2*r2 + r3*r3;
    #pragma unroll
    for (int off = 16; off > 0; off >>= 1)
        ls += __shfl_down_sync(0xffffffffu, ls, off);
    if ((t & 31) == 0) s_red[t>>5] = ls;
    __syncthreads();
    if (t == 0) {
        float tot = 0.f;
        #pragma unroll
        for (int i = 0; i < 8; i++) tot += s_red[i];
        atomicAdd(&g_sums[b], tot);
    }
}

// ---------------------------------------------------------------------------
// Final: out = net_input + r * min(1, k/(||r||+eps)), k = exp(alpha)*stdn*256
// ---------------------------------------------------------------------------
__global__ void final_kernel(const float* __restrict__ net_input,
                             const float* __restrict__ stdn,
                             const float* __restrict__ alpha,
                             float* __restrict__ out) {
    int i = blockIdx.x*256 + threadIdx.x;
    if (i >= NPIX) return;
    int b = i >> 16;
    float k = expf(alpha[0]) * stdn[b] * 256.f;  // sqrt(65536)=256
    float nr = sqrtf(g_sums[b]);
    float s = fminf(1.f, k / (nr + 1e-12f));
    out[i] = fmaf(g_r[i], s, net_input[i]);
}

extern "C" void kernel_launch(void* const* d_in, const int* in_sizes, int n_in,
                              void* d_out, int out_size) {
    const float* input     = (const float*)d_in[0];
    const float* stdn      = (const float*)d_in[1];
    // d_in[2] = rbf_data (unused; its grid is baked into the LUT)
    const float* net_input = (const float*)d_in[3];
    const float* cw        = (const float*)d_in[4];
    const float* scale_f   = (const float*)d_in[5];
    const float* alpha     = (const float*)d_in[6];
    const float* rbfw      = (const float*)d_in[7];
    const float* rbfc      = (const float*)d_in[8];
    float* out = (float*)d_out;

    prep_kernel<<<NF, 256>>>(cw, scale_f, rbfw, rbfc);
    main_kernel<<<dim3(8, 8, NB), 256>>>(input, net_input);
    final_kernel<<<(NPIX + 255)/256, 256>>>(net_input, stdn, alpha, out);
}

// round 3
// speedup vs baseline: 1.1632x; 1.1632x over previous
#include <cuda_runtime.h>
#include <math.h>

#define NB 16
#define NF 48
#define NM 51
#define HH 256
#define WW 256
#define LUTN 3201
#define LUTS 3200          // float2 slots (value, slope)
#define NPIX (NB*HH*WW)

// scratch (no allocations allowed)
__device__ float  g_wn[NF*49];
__device__ float2 g_lut2[NF*LUTS];
__device__ float  g_sums[NB];
__device__ float  g_r[NPIX];

// ---------------------------------------------------------------------------
// Prep: grid (NF, 8). Each (f, chunk) block builds 400 float2 LUT slots.
// chunk==0 blocks also normalize that filter's conv weights; f<NB zero sums.
// ---------------------------------------------------------------------------
__global__ void prep_kernel(const float* __restrict__ cw,
                            const float* __restrict__ scale_f,
                            const float* __restrict__ rbfw,
                            const float* __restrict__ rbfc) {
    int f = blockIdx.x;
    int c = blockIdx.y;          // 0..7, 400 slots each
    int t = threadIdx.x;
    __shared__ float s_wm[NM];
    __shared__ float s_c[NM];
    __shared__ float s_val[401];
    __shared__ float sw[49];
    __shared__ float s_norm[2];

    if (t < NM) { s_wm[t] = rbfw[f*NM + t]; s_c[t] = rbfc[t]; }
    if (c == 0) {
        if (t < 49) sw[t] = cw[f*49 + t];
        if (t == 0 && f < NB) g_sums[f] = 0.f;
    }
    __syncthreads();

    int base = c * 400;
    for (int j = t; j < 401; j += 256) {
        float x = -100.f + (float)(base + j) * 0.0625f;
        float a0 = 0.f, a1 = 0.f, a2 = 0.f, a3 = 0.f;
        int m = 0;
        for (; m + 4 <= NM; m += 4) {
            float d0 = x - s_c[m+0]; a0 = fmaf(s_wm[m+0], __expf(-0.01f*d0*d0), a0);
            float d1 = x - s_c[m+1]; a1 = fmaf(s_wm[m+1], __expf(-0.01f*d1*d1), a1);
            float d2 = x - s_c[m+2]; a2 = fmaf(s_wm[m+2], __expf(-0.01f*d2*d2), a2);
            float d3 = x - s_c[m+3]; a3 = fmaf(s_wm[m+3], __expf(-0.01f*d3*d3), a3);
        }
        for (; m < NM; m++) {
            float d = x - s_c[m]; a0 = fmaf(s_wm[m], __expf(-0.01f*d*d), a0);
        }
        s_val[j] = (a0 + a1) + (a2 + a3);
    }
    if (c == 0 && t == 0) {
        float mn = 0.f;
        for (int i = 0; i < 49; i++) mn += sw[i];
        mn *= (1.f/49.f);
        float ss = 0.f;
        for (int i = 0; i < 49; i++) { float v = sw[i]-mn; ss += v*v; }
        s_norm[0] = mn;
        s_norm[1] = scale_f[f] / (sqrtf(ss) + 1e-12f);
    }
    __syncthreads();
    for (int j = t; j < 400; j += 256) {
        float v0 = s_val[j], v1 = s_val[j+1];
        g_lut2[f*LUTS + base + j] = make_float2(v0, v1 - v0);
    }
    if (c == 0 && t < 49) g_wn[f*49 + t] = (sw[t] - s_norm[0]) * s_norm[1];
}

// ---------------------------------------------------------------------------
// Main fused kernel: fwd conv -> RBF LUT -> transpose conv -> residual r.
// One CTA = 32x32 output tile, 256 threads, 3 CTAs/SM.
// Double-buffered activation tile: ONE __syncthreads per filter.
// ---------------------------------------------------------------------------
__global__ void __launch_bounds__(256, 3)
main_kernel(const float* __restrict__ input, const float* __restrict__ net_input) {
    __shared__ float s_in[44][48];        // input halo tile (stride 48)
    __shared__ float s_a[2][38][40];      // double-buffered activation
    __shared__ float s_wall[NF*49];
    __shared__ float s_red[8];

    int t = threadIdx.x;
    int b = blockIdx.z;
    int ty0 = blockIdx.y << 5;
    int tx0 = blockIdx.x << 5;
    const float* inb = input + b*(HH*WW);

    for (int idx = t; idx < 44*44; idx += 256) {
        int iy = idx / 44, ix = idx - iy*44;
        int gy = ty0 - 6 + iy, gx = tx0 - 6 + ix;
        gy = gy < 0 ? -1-gy : (gy > 255 ? 511-gy : gy);
        gx = gx < 0 ? -1-gx : (gx > 255 ? 511-gx : gx);
        s_in[iy][ix] = inb[(gy<<8) + gx];
    }
    for (int idx = t; idx < NF*49; idx += 256) s_wall[idx] = g_wn[idx];

    float acc0=0.f, acc1=0.f, acc2=0.f, acc3=0.f;
    int orow = t >> 3;             // 0..31
    int ocol = (t & 7) << 2;       // 0..28

    int zr = t / 5;                // z tasks: 38 rows x 5 strips of 8
    int zg = (t - zr*5) << 3;
    bool zact = (t < 190);
    int zgr = ty0 - 3 + zr;
    int zgc0 = tx0 - 3 + zg;
    bool rowok = (zgr >= 0) && (zgr < 256);
    unsigned cmask = 0u;
    #pragma unroll
    for (int k = 0; k < 8; k++) {
        int zgc = zgc0 + k;
        if (rowok && zgc >= 0 && zgc < 256) cmask |= (1u << k);
    }

    __syncthreads();   // tiles + weights ready

    for (int f = 0; f < NF; f++) {
        const float* wf = &s_wall[f*49];
        float (*bufw)[40] = s_a[f & 1];
        if (zact) {
            const float2* lutf = g_lut2 + f*LUTS;
            float z0=0,z1=0,z2=0,z3=0,z4=0,z5=0,z6=0,z7=0;
            #pragma unroll
            for (int u = 0; u < 7; u++) {
                const float* rp = &s_in[zr+u][zg];
                float4 p0 = *(const float4*)(rp);
                float4 p1 = *(const float4*)(rp+4);
                float4 p2 = *(const float4*)(rp+8);
                float2 p3 = *(const float2*)(rp+12);
                float vals[14] = {p0.x,p0.y,p0.z,p0.w, p1.x,p1.y,p1.z,p1.w,
                                  p2.x,p2.y,p2.z,p2.w, p3.x,p3.y};
                #pragma unroll
                for (int v = 0; v < 7; v++) {
                    float w = wf[u*7+v];
                    z0 = fmaf(vals[v+0], w, z0);
                    z1 = fmaf(vals[v+1], w, z1);
                    z2 = fmaf(vals[v+2], w, z2);
                    z3 = fmaf(vals[v+3], w, z3);
                    z4 = fmaf(vals[v+4], w, z4);
                    z5 = fmaf(vals[v+5], w, z5);
                    z6 = fmaf(vals[v+6], w, z6);
                    z7 = fmaf(vals[v+7], w, z7);
                }
            }
            float zv[8] = {z0,z1,z2,z3,z4,z5,z6,z7};
            #pragma unroll
            for (int k = 0; k < 8; k++) {
                float tf = fminf(fmaxf(fmaf(zv[k], 16.f, 1600.f), 0.f), 3200.f);
                int i0 = min((int)tf, 3199);
                float fr = tf - (float)i0;
                float2 e = __ldg(lutf + i0);
                float a = fmaf(fr, e.y, e.x);
                if (!((cmask >> k) & 1u)) a = 0.f;
                bufw[zr][zg+k] = a;
            }
        }
        __syncthreads();   // activation(f) ready; also fences buffer reuse
        const float (*bufr)[40] = s_a[f & 1];
        #pragma unroll
        for (int uu = 0; uu < 7; uu++) {
            const float* rp = &bufr[orow+uu][ocol];
            float4 p0 = *(const float4*)(rp);
            float4 p1 = *(const float4*)(rp+4);
            float2 p2 = *(const float2*)(rp+8);
            float vals[10] = {p0.x,p0.y,p0.z,p0.w, p1.x,p1.y,p1.z,p1.w, p2.x,p2.y};
            #pragma unroll
            for (int vv = 0; vv < 7; vv++) {
                float w = wf[(6-uu)*7 + (6-vv)];
                acc0 = fmaf(vals[vv+0], w, acc0);
                acc1 = fmaf(vals[vv+1], w, acc1);
                acc2 = fmaf(vals[vv+2], w, acc2);
                acc3 = fmaf(vals[vv+3], w, acc3);
            }
        }
    }

    int gy = ty0 + orow;
    int gx = tx0 + ocol;
    int base = (gy<<8) + gx;
    const float* nb_ = net_input + b*(HH*WW);
    float4 iv = *(const float4*)(inb + base);
    float4 nv = *(const float4*)(nb_ + base);
    float r0 = iv.x - acc0 - nv.x;
    float r1 = iv.y - acc1 - nv.y;
    float r2 = iv.z - acc2 - nv.z;
    float r3 = iv.w - acc3 - nv.w;
    float4 rv; rv.x=r0; rv.y=r1; rv.z=r2; rv.w=r3;
    *(float4*)(g_r + b*(HH*WW) + base) = rv;
    float ls = r0*r0 + r1*r1 + r2*r2 + r3*r3;
    #pragma unroll
    for (int off = 16; off > 0; off >>= 1)
        ls += __shfl_down_sync(0xffffffffu, ls, off);
    if ((t & 31) == 0) s_red[t>>5] = ls;
    __syncthreads();
    if (t == 0) {
        float tot = 0.f;
        #pragma unroll
        for (int i = 0; i < 8; i++) tot += s_red[i];
        atomicAdd(&g_sums[b], tot);
    }
}

// ---------------------------------------------------------------------------
// Final: out = net_input + r * min(1, k/(||r||+eps)), k = exp(alpha)*stdn*256
// ---------------------------------------------------------------------------
__global__ void final_kernel(const float* __restrict__ net_input,
                             const float* __restrict__ stdn,
                             const float* __restrict__ alpha,
                             float* __restrict__ out) {
    int i4 = blockIdx.x*256 + threadIdx.x;
    if (i4 >= NPIX/4) return;
    int b = i4 >> 14;   // 16384 float4s per batch image
    float k = expf(alpha[0]) * stdn[b] * 256.f;   // sqrt(65536)=256
    float nr = sqrtf(g_sums[b]);
    float s = fminf(1.f, k / (nr + 1e-12f));
    float4 rv = ((const float4*)g_r)[i4];
    float4 nv = ((const float4*)net_input)[i4];
    float4 ov;
    ov.x = fmaf(rv.x, s, nv.x);
    ov.y = fmaf(rv.y, s, nv.y);
    ov.z = fmaf(rv.z, s, nv.z);
    ov.w = fmaf(rv.w, s, nv.w);
    ((float4*)out)[i4] = ov;
}

extern "C" void kernel_launch(void* const* d_in, const int* in_sizes, int n_in,
                              void* d_out, int out_size) {
    const float* input     = (const float*)d_in[0];
    const float* stdn      = (const float*)d_in[1];
    // d_in[2] = rbf_data (grid baked into LUT)
    const float* net_input = (const float*)d_in[3];
    const float* cw        = (const float*)d_in[4];
    const float* scale_f   = (const float*)d_in[5];
    const float* alpha     = (const float*)d_in[6];
    const float* rbfw      = (const float*)d_in[7];
    const float* rbfc      = (const float*)d_in[8];
    float* out = (float*)d_out;

    prep_kernel<<<dim3(NF, 8), 256>>>(cw, scale_f, rbfw, rbfc);
    main_kernel<<<dim3(8, 8, NB), 256>>>(input, net_input);
    final_kernel<<<(NPIX/4 + 255)/256, 256>>>(net_input, stdn, alpha, out);
}

// round 4
// speedup vs baseline: 1.6311x; 1.4022x over previous
#include <cuda_runtime.h>
#include <math.h>

#define NB 16
#define NF 48
#define NM 51
#define HH 256
#define WW 256
#define LUTS 3200          // float2 slots (value, slope)
#define NPIX (NB*HH*WW)

// scratch (no allocations allowed)
__device__ float  g_wn[NF*49];
__device__ float2 g_lut2[NF*LUTS];
__device__ float  g_sums[NB];
__device__ float  g_r[NPIX];

// ---------------------------------------------------------------------------
// Prep: grid (NF, 8). Each (f, chunk) block builds 400 float2 LUT slots.
// chunk==0 blocks also normalize that filter's conv weights; f<NB zero sums.
// ---------------------------------------------------------------------------
__global__ void prep_kernel(const float* __restrict__ cw,
                            const float* __restrict__ scale_f,
                            const float* __restrict__ rbfw,
                            const float* __restrict__ rbfc) {
    int f = blockIdx.x;
    int c = blockIdx.y;          // 0..7, 400 slots each
    int t = threadIdx.x;
    __shared__ float s_wm[NM];
    __shared__ float s_c[NM];
    __shared__ float s_val[401];
    __shared__ float sw[49];
    __shared__ float s_norm[2];

    if (t < NM) { s_wm[t] = rbfw[f*NM + t]; s_c[t] = rbfc[t]; }
    if (c == 0) {
        if (t < 49) sw[t] = cw[f*49 + t];
        if (t == 0 && f < NB) g_sums[f] = 0.f;
    }
    __syncthreads();

    int base = c * 400;
    for (int j = t; j < 401; j += 256) {
        float x = -100.f + (float)(base + j) * 0.0625f;
        float a0 = 0.f, a1 = 0.f, a2 = 0.f, a3 = 0.f;
        int m = 0;
        for (; m + 4 <= NM; m += 4) {
            float d0 = x - s_c[m+0]; a0 = fmaf(s_wm[m+0], __expf(-0.01f*d0*d0), a0);
            float d1 = x - s_c[m+1]; a1 = fmaf(s_wm[m+1], __expf(-0.01f*d1*d1), a1);
            float d2 = x - s_c[m+2]; a2 = fmaf(s_wm[m+2], __expf(-0.01f*d2*d2), a2);
            float d3 = x - s_c[m+3]; a3 = fmaf(s_wm[m+3], __expf(-0.01f*d3*d3), a3);
        }
        for (; m < NM; m++) {
            float d = x - s_c[m]; a0 = fmaf(s_wm[m], __expf(-0.01f*d*d), a0);
        }
        s_val[j] = (a0 + a1) + (a2 + a3);
    }
    if (c == 0 && t == 0) {
        float mn = 0.f;
        for (int i = 0; i < 49; i++) mn += sw[i];
        mn *= (1.f/49.f);
        float ss = 0.f;
        for (int i = 0; i < 49; i++) { float v = sw[i]-mn; ss += v*v; }
        s_norm[0] = mn;
        s_norm[1] = scale_f[f] / (sqrtf(ss) + 1e-12f);
    }
    __syncthreads();
    for (int j = t; j < 400; j += 256) {
        float v0 = s_val[j], v1 = s_val[j+1];
        g_lut2[f*LUTS + base + j] = make_float2(v0, v1 - v0);
    }
    if (c == 0 && t < 49) g_wn[f*49 + t] = (sw[t] - s_norm[0]) * s_norm[1];
}

// ---------------------------------------------------------------------------
// Main fused kernel: fwd conv -> RBF LUT -> transpose conv -> residual r.
// One CTA = 32x32 output tile, 256 threads, 4 CTAs/SM.
// TWO filters per barrier phase (24 barriers), double-buffered pair tiles.
// z-phase input loads shared across the filter pair.
// ---------------------------------------------------------------------------
__global__ void __launch_bounds__(256, 4)
main_kernel(const float* __restrict__ input, const float* __restrict__ net_input) {
    __shared__ float s_in[44][48];          // input halo tile (stride 48)
    __shared__ float s_a[2][2][38][40];     // [buf][filter-in-pair][..][..]
    __shared__ float s_wall[NF*49];
    __shared__ float s_red[8];

    int t = threadIdx.x;
    int b = blockIdx.z;
    int ty0 = blockIdx.y << 5;
    int tx0 = blockIdx.x << 5;
    const float* inb = input + b*(HH*WW);

    for (int idx = t; idx < 44*44; idx += 256) {
        int iy = idx / 44, ix = idx - iy*44;
        int gy = ty0 - 6 + iy, gx = tx0 - 6 + ix;
        gy = gy < 0 ? -1-gy : (gy > 255 ? 511-gy : gy);
        gx = gx < 0 ? -1-gx : (gx > 255 ? 511-gx : gx);
        s_in[iy][ix] = inb[(gy<<8) + gx];
    }
    for (int idx = t; idx < NF*49; idx += 256) s_wall[idx] = g_wn[idx];

    float acc0=0.f, acc1=0.f, acc2=0.f, acc3=0.f;
    int orow = t >> 3;             // 0..31
    int ocol = (t & 7) << 2;       // 0..28

    int zr = t / 5;                // z tasks: 38 rows x 5 strips of 8
    int zg = (t - zr*5) << 3;
    bool zact = (t < 190);
    int zgr = ty0 - 3 + zr;
    int zgc0 = tx0 - 3 + zg;
    bool rowok = (zgr >= 0) && (zgr < 256);
    unsigned cmask = 0u;
    #pragma unroll
    for (int k = 0; k < 8; k++) {
        int zgc = zgc0 + k;
        if (rowok && zgc >= 0 && zgc < 256) cmask |= (1u << k);
    }

    __syncthreads();   // tiles + weights ready

    for (int p = 0; p < NF/2; p++) {
        int f0 = p << 1;
        const float* wfa = &s_wall[f0*49];
        const float* wfb = wfa + 49;
        int bsel = p & 1;
        if (zact) {
            float za0=0,za1=0,za2=0,za3=0,za4=0,za5=0,za6=0,za7=0;
            float zb0=0,zb1=0,zb2=0,zb3=0,zb4=0,zb5=0,zb6=0,zb7=0;
            #pragma unroll
            for (int u = 0; u < 7; u++) {
                const float* rp = &s_in[zr+u][zg];
                float4 p0 = *(const float4*)(rp);
                float4 p1 = *(const float4*)(rp+4);
                float4 p2 = *(const float4*)(rp+8);
                float2 p3 = *(const float2*)(rp+12);
                float vals[14] = {p0.x,p0.y,p0.z,p0.w, p1.x,p1.y,p1.z,p1.w,
                                  p2.x,p2.y,p2.z,p2.w, p3.x,p3.y};
                #pragma unroll
                for (int v = 0; v < 7; v++) {
                    float wa = wfa[u*7+v];
                    float wb = wfb[u*7+v];
                    za0 = fmaf(vals[v+0], wa, za0);  zb0 = fmaf(vals[v+0], wb, zb0);
                    za1 = fmaf(vals[v+1], wa, za1);  zb1 = fmaf(vals[v+1], wb, zb1);
                    za2 = fmaf(vals[v+2], wa, za2);  zb2 = fmaf(vals[v+2], wb, zb2);
                    za3 = fmaf(vals[v+3], wa, za3);  zb3 = fmaf(vals[v+3], wb, zb3);
                    za4 = fmaf(vals[v+4], wa, za4);  zb4 = fmaf(vals[v+4], wb, zb4);
                    za5 = fmaf(vals[v+5], wa, za5);  zb5 = fmaf(vals[v+5], wb, zb5);
                    za6 = fmaf(vals[v+6], wa, za6);  zb6 = fmaf(vals[v+6], wb, zb6);
                    za7 = fmaf(vals[v+7], wa, za7);  zb7 = fmaf(vals[v+7], wb, zb7);
                }
            }
            float zva[8] = {za0,za1,za2,za3,za4,za5,za6,za7};
            float zvb[8] = {zb0,zb1,zb2,zb3,zb4,zb5,zb6,zb7};
            const float2* luta = g_lut2 + f0*LUTS;
            const float2* lutb = luta + LUTS;
            #pragma unroll
            for (int k = 0; k < 8; k++) {
                float tfa = fminf(fmaxf(fmaf(zva[k], 16.f, 1600.f), 0.f), 3200.f);
                int ia = min((int)tfa, 3199);
                float fra = tfa - (float)ia;
                float2 ea = __ldg(luta + ia);
                float aa = fmaf(fra, ea.y, ea.x);
                if (!((cmask >> k) & 1u)) aa = 0.f;
                s_a[bsel][0][zr][zg+k] = aa;

                float tfb = fminf(fmaxf(fmaf(zvb[k], 16.f, 1600.f), 0.f), 3200.f);
                int ib = min((int)tfb, 3199);
                float frb = tfb - (float)ib;
                float2 eb = __ldg(lutb + ib);
                float ab = fmaf(frb, eb.y, eb.x);
                if (!((cmask >> k) & 1u)) ab = 0.f;
                s_a[bsel][1][zr][zg+k] = ab;
            }
        }
        __syncthreads();   // both activations of the pair ready
        #pragma unroll
        for (int half = 0; half < 2; half++) {
            const float (*bufr)[40] = s_a[bsel][half];
            const float* wf = half ? wfb : wfa;
            #pragma unroll
            for (int uu = 0; uu < 7; uu++) {
                const float* rp = &bufr[orow+uu][ocol];
                float4 q0 = *(const float4*)(rp);
                float4 q1 = *(const float4*)(rp+4);
                float2 q2 = *(const float2*)(rp+8);
                float vals[10] = {q0.x,q0.y,q0.z,q0.w, q1.x,q1.y,q1.z,q1.w, q2.x,q2.y};
                #pragma unroll
                for (int vv = 0; vv < 7; vv++) {
                    float w = wf[(6-uu)*7 + (6-vv)];
                    acc0 = fmaf(vals[vv+0], w, acc0);
                    acc1 = fmaf(vals[vv+1], w, acc1);
                    acc2 = fmaf(vals[vv+2], w, acc2);
                    acc3 = fmaf(vals[vv+3], w, acc3);
                }
            }
        }
        // no second barrier: next pair writes the OTHER buffer set
    }

    int gy = ty0 + orow;
    int gx = tx0 + ocol;
    int base = (gy<<8) + gx;
    const float* nb_ = net_input + b*(HH*WW);
    float4 iv = *(const float4*)(inb + base);
    float4 nv = *(const float4*)(nb_ + base);
    float r0 = iv.x - acc0 - nv.x;
    float r1 = iv.y - acc1 - nv.y;
    float r2 = iv.z - acc2 - nv.z;
    float r3 = iv.w - acc3 - nv.w;
    float4 rv; rv.x=r0; rv.y=r1; rv.z=r2; rv.w=r3;
    *(float4*)(g_r + b*(HH*WW) + base) = rv;
    float ls = r0*r0 + r1*r1 + r2*r2 + r3*r3;
    #pragma unroll
    for (int off = 16; off > 0; off >>= 1)
        ls += __shfl_down_sync(0xffffffffu, ls, off);
    if ((t & 31) == 0) s_red[t>>5] = ls;
    __syncthreads();
    if (t == 0) {
        float tot = 0.f;
        #pragma unroll
        for (int i = 0; i < 8; i++) tot += s_red[i];
        atomicAdd(&g_sums[b], tot);
    }
}

// ---------------------------------------------------------------------------
// Final: out = net_input + r * min(1, k/(||r||+eps)), k = exp(alpha)*stdn*256
// ---------------------------------------------------------------------------
__global__ void final_kernel(const float* __restrict__ net_input,
                             const float* __restrict__ stdn,
                             const float* __restrict__ alpha,
                             float* __restrict__ out) {
    int i4 = blockIdx.x*256 + threadIdx.x;
    if (i4 >= NPIX/4) return;
    int b = i4 >> 14;   // 16384 float4s per batch image
    float k = expf(alpha[0]) * stdn[b] * 256.f;   // sqrt(65536)=256
    float nr = sqrtf(g_sums[b]);
    float s = fminf(1.f, k / (nr + 1e-12f));
    float4 rv = ((const float4*)g_r)[i4];
    float4 nv = ((const float4*)net_input)[i4];
    float4 ov;
    ov.x = fmaf(rv.x, s, nv.x);
    ov.y = fmaf(rv.y, s, nv.y);
    ov.z = fmaf(rv.z, s, nv.z);
    ov.w = fmaf(rv.w, s, nv.w);
    ((float4*)out)[i4] = ov;
}

extern "C" void kernel_launch(void* const* d_in, const int* in_sizes, int n_in,
                              void* d_out, int out_size) {
    const float* input     = (const float*)d_in[0];
    const float* stdn      = (const float*)d_in[1];
    // d_in[2] = rbf_data (grid baked into LUT)
    const float* net_input = (const float*)d_in[3];
    const float* cw        = (const float*)d_in[4];
    const float* scale_f   = (const float*)d_in[5];
    const float* alpha     = (const float*)d_in[6];
    const float* rbfw      = (const float*)d_in[7];
    const float* rbfc      = (const float*)d_in[8];
    float* out = (float*)d_out;

    prep_kernel<<<dim3(NF, 8), 256>>>(cw, scale_f, rbfw, rbfc);
    main_kernel<<<dim3(8, 8, NB), 256>>>(input, net_input);
    final_kernel<<<(NPIX/4 + 255)/256, 256>>>(net_input, stdn, alpha, out);
}